// round 6
// baseline (speedup 1.0000x reference)
#include <cuda_runtime.h>

// Problem constants
#define BSZ   4
#define CSQ   1024
#define PSQ   1024
#define DIN   1024
#define NH    16
#define HDIM  64
#define TT    2048        // T = CS + PS
#define LQG   4096        // BSZ*CSQ global query rows
#define HD    1024        // NH*HDIM
#define SCALE 0.125f      // 1/sqrt(64)

// ---------------------------------------------------------------------------
// Scratch (device globals; no dynamic allocation allowed)
// ---------------------------------------------------------------------------
__device__ float g_q [(size_t)LQG * HD];                 //  16.8 MB  q_tfmd
__device__ float g_kv[(size_t)BSZ * TT * 2 * HD];        //  67 MB    [k | v]
__device__ float g_p [(size_t)TT * HD];                  //   8.4 MB  p_tfmd
__device__ float g_P [(size_t)NH * LQG * TT];            // 512 MB    (q+v)@p^T per head
__device__ float g_S [(size_t)BSZ * NH * CSQ * TT];      // 512 MB    attention scores
__device__ float g_ao[(size_t)LQG * HD];                 //  16.8 MB  attn output (pre W_out)

// ---------------------------------------------------------------------------
// tf32 helpers
// ---------------------------------------------------------------------------
__device__ __forceinline__ float tf32r(float x) {
    float y;
    asm("cvt.rna.tf32.f32 %0, %1;" : "=f"(y) : "f"(x));
    return y;
}

// D += A(16x8 row) * B(8x8 col)
__device__ __forceinline__ void mma8(float* d, const float* a, const float* b) {
    asm volatile(
        "mma.sync.aligned.m16n8k8.row.col.f32.tf32.tf32.f32 "
        "{%0,%1,%2,%3}, {%4,%5,%6,%7}, {%8,%9}, {%0,%1,%2,%3};"
        : "+f"(d[0]), "+f"(d[1]), "+f"(d[2]), "+f"(d[3])
        : "r"(__float_as_uint(a[0])), "r"(__float_as_uint(a[1])),
          "r"(__float_as_uint(a[2])), "r"(__float_as_uint(a[3])),
          "r"(__float_as_uint(b[0])), "r"(__float_as_uint(b[1])));
}

// Fragment loads from padded SMEM tiles (row = k, col = m/n, pitch 136).
#define LOAD_AFRAG(a, As, kr, m0, ms)              \
    do {                                           \
        (a)[0] = (As)[(kr)    ][(m0) + (ms)    ];  \
        (a)[1] = (As)[(kr)    ][(m0) + (ms) + 8];  \
        (a)[2] = (As)[(kr) + 4][(m0) + (ms)    ];  \
        (a)[3] = (As)[(kr) + 4][(m0) + (ms) + 8];  \
    } while (0)
#define LOAD_BFRAG(b, Bs, kr, n0, ms)              \
    do {                                           \
        (b)[0] = (Bs)[(kr)    ][(n0) + (ms)];      \
        (b)[1] = (Bs)[(kr) + 4][(n0) + (ms)];      \
    } while (0)

// ---------------------------------------------------------------------------
// Generic 128x128 tf32 GEMM, row-major A(MxK) * B(KxN) -> C(MxN), K%16==0.
// MODE 0: A plain. MODE 1: A rows = virtual concat(memory, input_) over seq.
// Double-buffered SMEM + register-staged prefetch; ONE sync per k-tile.
// 256 threads = 8 warps in 2(m) x 4(n); warp tile 64x32 = 4x4 m16n8 tiles.
// ---------------------------------------------------------------------------
template <int MODE>
__global__ void __launch_bounds__(256, 2) gemm_tf32(
    const float* __restrict__ A, const float* __restrict__ A2,
    const float* __restrict__ B, float* __restrict__ C,
    int M, int N, int K)
{
    __shared__ float As[2][16][136];
    __shared__ float Bs[2][16][136];
    const int tid  = threadIdx.x;
    const int lane = tid & 31;
    const int w    = tid >> 5;
    const int wm   = (w >> 2) * 64;
    const int wn   = (w & 3) * 32;
    const int bm   = blockIdx.y * 128;
    const int bn   = blockIdx.x * 128;

    const int ar = tid & 127;
    const int ak = (tid >> 7) * 8;
    const float* arow;
    if (MODE == 0) {
        arow = A + (size_t)(bm + ar) * K;
    } else {
        int row = bm + ar;
        int b   = row / TT;
        int r   = row - b * TT;
        arow = (r < PSQ) ? A  + (size_t)(b * PSQ + r)         * K
                         : A2 + (size_t)(b * CSQ + (r - PSQ)) * K;
    }
    const int br = tid >> 4;
    const int bc = (tid & 15) * 8;
    const float* bp = B + (size_t)br * N + bn + bc;

    float acc[4][4][4] = {};
    float4 ra0, ra1, rb0, rb1;

#define GL(k0) do {                                              \
        ra0 = *(const float4*)(arow + (k0) + ak);                \
        ra1 = *(const float4*)(arow + (k0) + ak + 4);            \
        rb0 = *(const float4*)(bp + (size_t)(k0) * N);           \
        rb1 = *(const float4*)(bp + (size_t)(k0) * N + 4);       \
    } while (0)
#define ST(pp) do {                                                        \
        As[pp][ak + 0][ar] = tf32r(ra0.x); As[pp][ak + 1][ar] = tf32r(ra0.y); \
        As[pp][ak + 2][ar] = tf32r(ra0.z); As[pp][ak + 3][ar] = tf32r(ra0.w); \
        As[pp][ak + 4][ar] = tf32r(ra1.x); As[pp][ak + 5][ar] = tf32r(ra1.y); \
        As[pp][ak + 6][ar] = tf32r(ra1.z); As[pp][ak + 7][ar] = tf32r(ra1.w); \
        Bs[pp][br][bc + 0] = tf32r(rb0.x); Bs[pp][br][bc + 1] = tf32r(rb0.y); \
        Bs[pp][br][bc + 2] = tf32r(rb0.z); Bs[pp][br][bc + 3] = tf32r(rb0.w); \
        Bs[pp][br][bc + 4] = tf32r(rb1.x); Bs[pp][br][bc + 5] = tf32r(rb1.y); \
        Bs[pp][br][bc + 6] = tf32r(rb1.z); Bs[pp][br][bc + 7] = tf32r(rb1.w); \
    } while (0)

    GL(0); ST(0); __syncthreads();
    int p = 0;
    for (int k0 = 0; k0 < K; k0 += 16) {
        const bool more = (k0 + 16 < K);
        if (more) GL(k0 + 16);
        float (*Asp)[136] = As[p];
        float (*Bsp)[136] = Bs[p];
#pragma unroll
        for (int kk = 0; kk < 16; kk += 8) {
            const int kr = kk + (lane & 3);
            const int ms = lane >> 2;
            float a[4][4], b[4][2];
#pragma unroll
            for (int t = 0; t < 4; t++) {
                LOAD_AFRAG(a[t], Asp, kr, wm + t * 16, ms);
                LOAD_BFRAG(b[t], Bsp, kr, wn + t * 8,  ms);
            }
#pragma unroll
            for (int mt = 0; mt < 4; mt++)
#pragma unroll
                for (int nt = 0; nt < 4; nt++)
                    mma8(acc[mt][nt], a[mt], b[nt]);
        }
        if (more) { ST(p ^ 1); __syncthreads(); p ^= 1; }
    }
#undef GL
#undef ST

#pragma unroll
    for (int mt = 0; mt < 4; mt++) {
        int r0 = bm + wm + mt * 16 + (lane >> 2);
#pragma unroll
        for (int nt = 0; nt < 4; nt++) {
            int c0 = bn + wn + nt * 8 + (lane & 3) * 2;
            *(float2*)&C[(size_t)r0 * N + c0]       = make_float2(acc[mt][nt][0], acc[mt][nt][1]);
            *(float2*)&C[(size_t)(r0 + 8) * N + c0] = make_float2(acc[mt][nt][2], acc[mt][nt][3]);
        }
    }
}

// ---------------------------------------------------------------------------
// P[h][L][jj] = sum_d (q[L,h,d]+v[h,d]) * p[jj,h,d]   (NT, K=64)
// Block 128x128 per head; double-buffered like gemm_tf32.
// ---------------------------------------------------------------------------
__global__ void __launch_bounds__(256, 2) pos_gemm_tf32(
    const float* __restrict__ q, const float* __restrict__ p,
    const float* __restrict__ vb, float* __restrict__ P)
{
    __shared__ float As[2][16][136];
    __shared__ float Bs[2][16][136];
    const int tid  = threadIdx.x;
    const int lane = tid & 31;
    const int w    = tid >> 5;
    const int wm   = (w >> 2) * 64;
    const int wn   = (w & 3) * 32;
    const int h    = blockIdx.z;
    const int L0   = blockIdx.y * 128;
    const int j0   = blockIdx.x * 128;

    const int ar = tid & 127;
    const int ak = (tid >> 7) * 8;
    const float* arow = q  + (size_t)(L0 + ar) * HD + h * HDIM + ak;
    const float* vrow = vb + h * HDIM + ak;
    const float* brow = p  + (size_t)(j0 + ar) * HD + h * HDIM + ak;

    float acc[4][4][4] = {};
    float4 ra0, ra1, rv0, rv1, rb0, rb1;

#define GL(k0) do {                                    \
        ra0 = *(const float4*)(arow + (k0));           \
        ra1 = *(const float4*)(arow + (k0) + 4);       \
        rv0 = *(const float4*)(vrow + (k0));           \
        rv1 = *(const float4*)(vrow + (k0) + 4);       \
        rb0 = *(const float4*)(brow + (k0));           \
        rb1 = *(const float4*)(brow + (k0) + 4);       \
    } while (0)
#define ST(pp) do {                                                                   \
        As[pp][ak + 0][ar] = tf32r(ra0.x + rv0.x); As[pp][ak + 1][ar] = tf32r(ra0.y + rv0.y); \
        As[pp][ak + 2][ar] = tf32r(ra0.z + rv0.z); As[pp][ak + 3][ar] = tf32r(ra0.w + rv0.w); \
        As[pp][ak + 4][ar] = tf32r(ra1.x + rv1.x); As[pp][ak + 5][ar] = tf32r(ra1.y + rv1.y); \
        As[pp][ak + 6][ar] = tf32r(ra1.z + rv1.z); As[pp][ak + 7][ar] = tf32r(ra1.w + rv1.w); \
        Bs[pp][ak + 0][ar] = tf32r(rb0.x); Bs[pp][ak + 1][ar] = tf32r(rb0.y);          \
        Bs[pp][ak + 2][ar] = tf32r(rb0.z); Bs[pp][ak + 3][ar] = tf32r(rb0.w);          \
        Bs[pp][ak + 4][ar] = tf32r(rb1.x); Bs[pp][ak + 5][ar] = tf32r(rb1.y);          \
        Bs[pp][ak + 6][ar] = tf32r(rb1.z); Bs[pp][ak + 7][ar] = tf32r(rb1.w);          \
    } while (0)

    GL(0); ST(0); __syncthreads();
    int p2 = 0;
#pragma unroll
    for (int k0 = 0; k0 < HDIM; k0 += 16) {
        const bool more = (k0 + 16 < HDIM);
        if (more) GL(k0 + 16);
        float (*Asp)[136] = As[p2];
        float (*Bsp)[136] = Bs[p2];
#pragma unroll
        for (int kk = 0; kk < 16; kk += 8) {
            const int kr = kk + (lane & 3);
            const int ms = lane >> 2;
            float a[4][4], b[4][2];
#pragma unroll
            for (int t = 0; t < 4; t++) {
                LOAD_AFRAG(a[t], Asp, kr, wm + t * 16, ms);
                LOAD_BFRAG(b[t], Bsp, kr, wn + t * 8,  ms);
            }
#pragma unroll
            for (int mt = 0; mt < 4; mt++)
#pragma unroll
                for (int nt = 0; nt < 4; nt++)
                    mma8(acc[mt][nt], a[mt], b[nt]);
        }
        if (more) { ST(p2 ^ 1); __syncthreads(); p2 ^= 1; }
    }
#undef GL
#undef ST

#pragma unroll
    for (int mt = 0; mt < 4; mt++) {
        int r0 = L0 + wm + mt * 16 + (lane >> 2);
#pragma unroll
        for (int nt = 0; nt < 4; nt++) {
            int c0 = j0 + wn + nt * 8 + (lane & 3) * 2;
            float* o = P + ((size_t)h * LQG + r0) * TT + c0;
            *(float2*)o            = make_float2(acc[mt][nt][0], acc[mt][nt][1]);
            *(float2*)(o + 8 * TT) = make_float2(acc[mt][nt][2], acc[mt][nt][3]);
        }
    }
}

// ---------------------------------------------------------------------------
// rel_shift gather: pos(b,i,j) with L = b*CS+i
// ---------------------------------------------------------------------------
__device__ __forceinline__ float pos_val(const float* __restrict__ Pm,
                                         int h, int L, int jj)
{
    int s  = jj + LQG - L;
    int n  = (s > TT) + (s > 2 * TT + 1);
    int jp = s - n * (TT + 1);
    int Lp = L + n;
    float pos = 0.f;
    if (jp > 0 && Lp < LQG)
        pos = Pm[((size_t)h * LQG + Lp) * TT + (jp - 1)];
    return pos;
}

// ---------------------------------------------------------------------------
// Scores: S[b,h,i,j] = (q+u)·k + rel_shift(P), masked. Block 128x128, K=64.
// ---------------------------------------------------------------------------
__global__ void __launch_bounds__(256, 2) score_gemm_tf32(
    const float* __restrict__ q, const float* __restrict__ kv,
    const float* __restrict__ ub, const float* __restrict__ Pm,
    float* __restrict__ S)
{
    __shared__ float As[2][16][136];
    __shared__ float Bs[2][16][136];
    const int tid  = threadIdx.x;
    const int lane = tid & 31;
    const int w    = tid >> 5;
    const int wm   = (w >> 2) * 64;
    const int wn   = (w & 3) * 32;
    const int bh   = blockIdx.z;
    const int b    = bh >> 4;
    const int h    = bh & 15;
    const int i0   = blockIdx.y * 128;
    const int j0   = blockIdx.x * 128;

    const int ar = tid & 127;
    const int ak = (tid >> 7) * 8;
    const float* arow = q  + (size_t)(b * CSQ + i0 + ar) * HD + h * HDIM + ak;
    const float* urow = ub + h * HDIM + ak;
    const float* brow = kv + ((size_t)b * TT + j0 + ar) * (2 * HD) + h * HDIM + ak;

    float acc[4][4][4] = {};
    float4 ra0, ra1, rv0, rv1, rb0, rb1;

#define GL(k0) do {                                    \
        ra0 = *(const float4*)(arow + (k0));           \
        ra1 = *(const float4*)(arow + (k0) + 4);       \
        rv0 = *(const float4*)(urow + (k0));           \
        rv1 = *(const float4*)(urow + (k0) + 4);       \
        rb0 = *(const float4*)(brow + (k0));           \
        rb1 = *(const float4*)(brow + (k0) + 4);       \
    } while (0)
#define ST(pp) do {                                                                   \
        As[pp][ak + 0][ar] = tf32r(ra0.x + rv0.x); As[pp][ak + 1][ar] = tf32r(ra0.y + rv0.y); \
        As[pp][ak + 2][ar] = tf32r(ra0.z + rv0.z); As[pp][ak + 3][ar] = tf32r(ra0.w + rv0.w); \
        As[pp][ak + 4][ar] = tf32r(ra1.x + rv1.x); As[pp][ak + 5][ar] = tf32r(ra1.y + rv1.y); \
        As[pp][ak + 6][ar] = tf32r(ra1.z + rv1.z); As[pp][ak + 7][ar] = tf32r(ra1.w + rv1.w); \
        Bs[pp][ak + 0][ar] = tf32r(rb0.x); Bs[pp][ak + 1][ar] = tf32r(rb0.y);          \
        Bs[pp][ak + 2][ar] = tf32r(rb0.z); Bs[pp][ak + 3][ar] = tf32r(rb0.w);          \
        Bs[pp][ak + 4][ar] = tf32r(rb1.x); Bs[pp][ak + 5][ar] = tf32r(rb1.y);          \
        Bs[pp][ak + 6][ar] = tf32r(rb1.z); Bs[pp][ak + 7][ar] = tf32r(rb1.w);          \
    } while (0)

    GL(0); ST(0); __syncthreads();
    int p2 = 0;
#pragma unroll
    for (int k0 = 0; k0 < HDIM; k0 += 16) {
        const bool more = (k0 + 16 < HDIM);
        if (more) GL(k0 + 16);
        float (*Asp)[136] = As[p2];
        float (*Bsp)[136] = Bs[p2];
#pragma unroll
        for (int kk = 0; kk < 16; kk += 8) {
            const int kr = kk + (lane & 3);
            const int ms = lane >> 2;
            float a[4][4], bq[4][2];
#pragma unroll
            for (int t = 0; t < 4; t++) {
                LOAD_AFRAG(a[t],  Asp, kr, wm + t * 16, ms);
                LOAD_BFRAG(bq[t], Bsp, kr, wn + t * 8,  ms);
            }
#pragma unroll
            for (int mt = 0; mt < 4; mt++)
#pragma unroll
                for (int nt = 0; nt < 4; nt++)
                    mma8(acc[mt][nt], a[mt], bq[nt]);
        }
        if (more) { ST(p2 ^ 1); __syncthreads(); p2 ^= 1; }
    }
#undef GL
#undef ST

#pragma unroll
    for (int mt = 0; mt < 4; mt++) {
        int ii_base = i0 + wm + mt * 16 + (lane >> 2);
#pragma unroll
        for (int nt = 0; nt < 4; nt++) {
            int jj0 = j0 + wn + nt * 8 + (lane & 3) * 2;
#pragma unroll
            for (int rr = 0; rr < 2; rr++) {
                int ii = ii_base + rr * 8;
                int L  = b * CSQ + ii;
                float v0, v1;
                if (jj0 > ii + PSQ)       v0 = -1e30f;
                else                      v0 = acc[mt][nt][rr * 2 + 0] + pos_val(Pm, h, L, jj0);
                if (jj0 + 1 > ii + PSQ)   v1 = -1e30f;
                else                      v1 = acc[mt][nt][rr * 2 + 1] + pos_val(Pm, h, L, jj0 + 1);
                float* so = S + ((size_t)(b * NH + h) * CSQ + ii) * TT + jj0;
                *(float2*)so = make_float2(v0, v1);
            }
        }
    }
}

// ---------------------------------------------------------------------------
// Row softmax over j (T=2048) of SCALE*score, in place. 1 block per row.
// float4-vectorized: thread t owns float4 slots {t, t+256}.
// ---------------------------------------------------------------------------
__global__ void __launch_bounds__(256) softmax_k(float* __restrict__ S)
{
    const int t = threadIdx.x;
    float4* x = (float4*)(S + (size_t)blockIdx.x * TT);
    float4 v0 = x[t];
    float4 v1 = x[t + 256];

    float m = fmaxf(fmaxf(fmaxf(v0.x, v0.y), fmaxf(v0.z, v0.w)),
                    fmaxf(fmaxf(v1.x, v1.y), fmaxf(v1.z, v1.w)));
#pragma unroll
    for (int o = 16; o > 0; o >>= 1)
        m = fmaxf(m, __shfl_xor_sync(0xffffffffu, m, o));
    __shared__ float red[8];
    if ((t & 31) == 0) red[t >> 5] = m;
    __syncthreads();
    float bm = red[0];
#pragma unroll
    for (int w = 1; w < 8; w++) bm = fmaxf(bm, red[w]);

    v0.x = __expf((v0.x - bm) * SCALE);  v0.y = __expf((v0.y - bm) * SCALE);
    v0.z = __expf((v0.z - bm) * SCALE);  v0.w = __expf((v0.w - bm) * SCALE);
    v1.x = __expf((v1.x - bm) * SCALE);  v1.y = __expf((v1.y - bm) * SCALE);
    v1.z = __expf((v1.z - bm) * SCALE);  v1.w = __expf((v1.w - bm) * SCALE);
    float s = v0.x + v0.y + v0.z + v0.w + v1.x + v1.y + v1.z + v1.w;
#pragma unroll
    for (int o = 16; o > 0; o >>= 1)
        s += __shfl_xor_sync(0xffffffffu, s, o);
    __syncthreads();
    if ((t & 31) == 0) red[t >> 5] = s;
    __syncthreads();
    float tot = 0.f;
#pragma unroll
    for (int w = 0; w < 8; w++) tot += red[w];
    float inv = 1.0f / tot;
    v0.x *= inv; v0.y *= inv; v0.z *= inv; v0.w *= inv;
    v1.x *= inv; v1.y *= inv; v1.z *= inv; v1.w *= inv;
    x[t]       = v0;
    x[t + 256] = v1;
}

// ---------------------------------------------------------------------------
// ao[b,i,h,:] = sum_j S[b,h,i,j] * v[b,j,h,:]
// Block 128x64; 8 warps in 4(m) x 2(n); warp 32x32 = 2x4 m16n8 tiles.
// K truncated by causality. Double-buffered SMEM, one sync per k-tile.
// ---------------------------------------------------------------------------
__global__ void __launch_bounds__(256, 2) awv_gemm_tf32(
    const float* __restrict__ S, const float* __restrict__ kv,
    float* __restrict__ ao)
{
    __shared__ float As[2][16][136];
    __shared__ float Bs[2][16][72];
    const int tid  = threadIdx.x;
    const int lane = tid & 31;
    const int w    = tid >> 5;
    const int wm   = (w >> 1) * 32;
    const int wn   = (w & 1) * 32;
    const int bh   = blockIdx.z;
    const int b    = bh >> 4;
    const int h    = bh & 15;
    const int i0   = blockIdx.y * 128;

    const int ar = tid & 127;
    const int ak = (tid >> 7) * 8;
    const float* arow = S + ((size_t)(b * NH + h) * CSQ + i0 + ar) * TT + ak;
    const int bkr = tid >> 4;          // k row 0..15
    const int bcc = (tid & 15) * 4;    // col quad
    const float* bbase = kv + ((size_t)b * TT + bkr) * (2 * HD) + HD + h * HDIM + bcc;

    float acc[2][4][4] = {};
    const int Kef = min(TT, i0 + 128 + PSQ);
    float4 ra0, ra1, rb;

#define GL(k0) do {                                                 \
        ra0 = *(const float4*)(arow + (k0));                        \
        ra1 = *(const float4*)(arow + (k0) + 4);                    \
        rb  = *(const float4*)(bbase + (size_t)(k0) * (2 * HD));    \
    } while (0)
#define ST(pp) do {                                                       \
        As[pp][ak + 0][ar] = tf32r(ra0.x); As[pp][ak + 1][ar] = tf32r(ra0.y); \
        As[pp][ak + 2][ar] = tf32r(ra0.z); As[pp][ak + 3][ar] = tf32r(ra0.w); \
        As[pp][ak + 4][ar] = tf32r(ra1.x); As[pp][ak + 5][ar] = tf32r(ra1.y); \
        As[pp][ak + 6][ar] = tf32r(ra1.z); As[pp][ak + 7][ar] = tf32r(ra1.w); \
        Bs[pp][bkr][bcc + 0] = tf32r(rb.x);                               \
        Bs[pp][bkr][bcc + 1] = tf32r(rb.y);                               \
        Bs[pp][bkr][bcc + 2] = tf32r(rb.z);                               \
        Bs[pp][bkr][bcc + 3] = tf32r(rb.w);                               \
    } while (0)

    GL(0); ST(0); __syncthreads();
    int p2 = 0;
    for (int k0 = 0; k0 < Kef; k0 += 16) {
        const bool more = (k0 + 16 < Kef);
        if (more) GL(k0 + 16);
        float (*Asp)[136] = As[p2];
        float (*Bsp)[72]  = Bs[p2];
#pragma unroll
        for (int kk = 0; kk < 16; kk += 8) {
            const int kr = kk + (lane & 3);
            const int ms = lane >> 2;
            float a[2][4], bq[4][2];
#pragma unroll
            for (int t = 0; t < 2; t++)
                LOAD_AFRAG(a[t], Asp, kr, wm + t * 16, ms);
#pragma unroll
            for (int t = 0; t < 4; t++)
                LOAD_BFRAG(bq[t], Bsp, kr, wn + t * 8, ms);
#pragma unroll
            for (int mt = 0; mt < 2; mt++)
#pragma unroll
                for (int nt = 0; nt < 4; nt++)
                    mma8(acc[mt][nt], a[mt], bq[nt]);
        }
        if (more) { ST(p2 ^ 1); __syncthreads(); p2 ^= 1; }
    }
#undef GL
#undef ST

#pragma unroll
    for (int mt = 0; mt < 2; mt++) {
        int r0 = i0 + wm + mt * 16 + (lane >> 2);
#pragma unroll
        for (int nt = 0; nt < 4; nt++) {
            int c0 = wn + nt * 8 + (lane & 3) * 2;
            float* o = ao + (size_t)(b * CSQ + r0) * HD + h * HDIM + c0;
            *(float2*)o            = make_float2(acc[mt][nt][0], acc[mt][nt][1]);
            *(float2*)(o + 8 * HD) = make_float2(acc[mt][nt][2], acc[mt][nt][3]);
        }
    }
}

// ---------------------------------------------------------------------------
// Launch: 8 kernels, default stream, graph-capturable.
// Inputs: input_, pos_embs, memory, u, v, W_kv, W_q, W_p, W_out, mask(unused).
// ---------------------------------------------------------------------------
extern "C" void kernel_launch(void* const* d_in, const int* in_sizes, int n_in,
                              void* d_out, int out_size)
{
    const float* input_ = (const float*)d_in[0];
    const float* pos    = (const float*)d_in[1];
    const float* memory = (const float*)d_in[2];
    const float* u      = (const float*)d_in[3];
    const float* v      = (const float*)d_in[4];
    const float* W_kv   = (const float*)d_in[5];
    const float* W_q    = (const float*)d_in[6];
    const float* W_p    = (const float*)d_in[7];
    const float* W_out  = (const float*)d_in[8];
    float* out = (float*)d_out;

    float *qb, *kvb, *pb, *Pb, *Sb, *aob;
    cudaGetSymbolAddress((void**)&qb,  g_q);
    cudaGetSymbolAddress((void**)&kvb, g_kv);
    cudaGetSymbolAddress((void**)&pb,  g_p);
    cudaGetSymbolAddress((void**)&Pb,  g_P);
    cudaGetSymbolAddress((void**)&Sb,  g_S);
    cudaGetSymbolAddress((void**)&aob, g_ao);

    dim3 thr(256);

    // q = input_ @ W_q                      (4096 x 1024 x 1024)
    gemm_tf32<0><<<dim3(HD / 128, LQG / 128), thr>>>(input_, nullptr, W_q, qb, LQG, HD, DIN);
    // kv = concat(memory, input_) @ W_kv    (8192 x 2048 x 1024)
    gemm_tf32<1><<<dim3(2 * HD / 128, (BSZ * TT) / 128), thr>>>(memory, input_, W_kv, kvb, BSZ * TT, 2 * HD, DIN);
    // p = pos_embs @ W_p                    (2048 x 1024 x 1024)
    gemm_tf32<0><<<dim3(HD / 128, TT / 128), thr>>>(pos, nullptr, W_p, pb, TT, HD, DIN);
    // P[h] = (q + v) @ p^T per head         (16 x 4096 x 2048 x 64)
    pos_gemm_tf32<<<dim3(TT / 128, LQG / 128, NH), thr>>>(qb, pb, v, Pb);
    // scores + rel-shift gather + mask
    score_gemm_tf32<<<dim3(TT / 128, CSQ / 128, BSZ * NH), thr>>>(qb, kvb, u, Pb, Sb);
    // softmax
    softmax_k<<<BSZ * NH * CSQ, thr>>>(Sb);
    // attn @ V
    awv_gemm_tf32<<<dim3(1, CSQ / 128, BSZ * NH), thr>>>(Sb, kvb, aob);
    // out = ao @ W_out                      (4096 x 1024 x 1024)
    gemm_tf32<0><<<dim3(DIN / 128, LQG / 128), thr>>>(aob, nullptr, W_out, out, LQG, DIN, HD);
}

// round 7
// speedup vs baseline: 1.2859x; 1.2859x over previous
#include <cuda_runtime.h>

// Problem constants
#define BSZ   4
#define CSQ   1024
#define PSQ   1024
#define DIN   1024
#define NH    16
#define HDIM  64
#define TT    2048        // T = CS + PS
#define LQG   4096        // BSZ*CSQ global query rows
#define HD    1024        // NH*HDIM
#define SCALE 0.125f      // 1/sqrt(64)

// ---------------------------------------------------------------------------
// Scratch (device globals; no dynamic allocation allowed)
// ---------------------------------------------------------------------------
__device__ float g_q [(size_t)LQG * HD];                 //  16.8 MB  q_tfmd
__device__ float g_kv[(size_t)BSZ * TT * 2 * HD];        //  67 MB    [k | v]
__device__ float g_p [(size_t)TT * HD];                  //   8.4 MB  p_tfmd
__device__ float g_P [(size_t)NH * LQG * TT];            // 512 MB    (q+v)@p^T per head
__device__ float g_S [(size_t)BSZ * NH * CSQ * TT];      // 512 MB    attention scores
__device__ float g_ao[(size_t)LQG * HD];                 //  16.8 MB  attn output (pre W_out)

// ---------------------------------------------------------------------------
// tf32 helpers
// ---------------------------------------------------------------------------
__device__ __forceinline__ float tf32r(float x) {
    float y;
    asm("cvt.rna.tf32.f32 %0, %1;" : "=f"(y) : "f"(x));
    return y;
}
__device__ __forceinline__ float4 tf32r4(float4 v) {
    return make_float4(tf32r(v.x), tf32r(v.y), tf32r(v.z), tf32r(v.w));
}

// D += A(16x8 row) * B(8x8 col)
__device__ __forceinline__ void mma8(float* d, const float* a, const float* b) {
    asm volatile(
        "mma.sync.aligned.m16n8k8.row.col.f32.tf32.tf32.f32 "
        "{%0,%1,%2,%3}, {%4,%5,%6,%7}, {%8,%9}, {%0,%1,%2,%3};"
        : "+f"(d[0]), "+f"(d[1]), "+f"(d[2]), "+f"(d[3])
        : "r"(__float_as_uint(a[0])), "r"(__float_as_uint(a[1])),
          "r"(__float_as_uint(a[2])), "r"(__float_as_uint(a[3])),
          "r"(__float_as_uint(b[0])), "r"(__float_as_uint(b[1])));
}

// ---------------------------------------------------------------------------
// Generic 128x128 tf32 GEMM, row-major A(MxK) * B(KxN) -> C(MxN), K%16==0.
// MODE 0: A plain. MODE 1: A rows = virtual concat(memory, input_) over seq.
// 128 threads = 4 warps in 2(m) x 2(n); warp tile 64x64 = 4x8 m16n8 tiles.
// Single SMEM buffer; global prefetch into regs overlaps the MMA block.
// ---------------------------------------------------------------------------
template <int MODE>
__global__ void __launch_bounds__(128) gemm_tf32(
    const float* __restrict__ A, const float* __restrict__ A2,
    const float* __restrict__ B, float* __restrict__ C,
    int M, int N, int K)
{
    __shared__ float As[16][136];
    __shared__ float Bs[16][136];
    const int tid  = threadIdx.x;
    const int lane = tid & 31;
    const int w    = tid >> 5;
    const int wm   = (w >> 1) * 64;
    const int wn   = (w & 1) * 64;
    const int bm   = blockIdx.y * 128;
    const int bn   = blockIdx.x * 128;

    // A loader: thread -> row (tid), 16 k floats (4x float4), transposed store
    const float* arow;
    if (MODE == 0) {
        arow = A + (size_t)(bm + tid) * K;
    } else {
        int row = bm + tid;
        int b   = row / TT;
        int r   = row - b * TT;
        arow = (r < PSQ) ? A  + (size_t)(b * PSQ + r)         * K
                         : A2 + (size_t)(b * CSQ + (r - PSQ)) * K;
    }
    // B loader: thread -> k row (tid>>3), col quads cq*4 + 32*i, STS.128
    const int br = tid >> 3;
    const int cq = tid & 7;
    const float* bp = B + (size_t)br * N + bn + cq * 4;

    float acc[4][8][4] = {};
    float4 sa[4], sb[4];

#define GL(k0) do {                                                  \
        sa[0] = *(const float4*)(arow + (k0));                       \
        sa[1] = *(const float4*)(arow + (k0) + 4);                   \
        sa[2] = *(const float4*)(arow + (k0) + 8);                   \
        sa[3] = *(const float4*)(arow + (k0) + 12);                  \
        sb[0] = *(const float4*)(bp + (size_t)(k0) * N);             \
        sb[1] = *(const float4*)(bp + (size_t)(k0) * N + 32);        \
        sb[2] = *(const float4*)(bp + (size_t)(k0) * N + 64);        \
        sb[3] = *(const float4*)(bp + (size_t)(k0) * N + 96);        \
    } while (0)
#define STORE() do {                                                 \
        As[0][tid]  = tf32r(sa[0].x); As[1][tid]  = tf32r(sa[0].y);  \
        As[2][tid]  = tf32r(sa[0].z); As[3][tid]  = tf32r(sa[0].w);  \
        As[4][tid]  = tf32r(sa[1].x); As[5][tid]  = tf32r(sa[1].y);  \
        As[6][tid]  = tf32r(sa[1].z); As[7][tid]  = tf32r(sa[1].w);  \
        As[8][tid]  = tf32r(sa[2].x); As[9][tid]  = tf32r(sa[2].y);  \
        As[10][tid] = tf32r(sa[2].z); As[11][tid] = tf32r(sa[2].w);  \
        As[12][tid] = tf32r(sa[3].x); As[13][tid] = tf32r(sa[3].y);  \
        As[14][tid] = tf32r(sa[3].z); As[15][tid] = tf32r(sa[3].w);  \
        *(float4*)&Bs[br][cq * 4]      = tf32r4(sb[0]);              \
        *(float4*)&Bs[br][cq * 4 + 32] = tf32r4(sb[1]);              \
        *(float4*)&Bs[br][cq * 4 + 64] = tf32r4(sb[2]);              \
        *(float4*)&Bs[br][cq * 4 + 96] = tf32r4(sb[3]);              \
    } while (0)

    GL(0); STORE(); __syncthreads();
    for (int k0 = 0; k0 < K; k0 += 16) {
        const bool more = (k0 + 16 < K);
        if (more) GL(k0 + 16);
#pragma unroll
        for (int kk = 0; kk < 16; kk += 8) {
            const int kr = kk + (lane & 3);
            const int ms = lane >> 2;
            float a[4][4], b[8][2];
#pragma unroll
            for (int mt = 0; mt < 4; mt++) {
                a[mt][0] = As[kr][wm + mt * 16 + ms];
                a[mt][1] = As[kr][wm + mt * 16 + ms + 8];
                a[mt][2] = As[kr + 4][wm + mt * 16 + ms];
                a[mt][3] = As[kr + 4][wm + mt * 16 + ms + 8];
            }
#pragma unroll
            for (int nt = 0; nt < 8; nt++) {
                b[nt][0] = Bs[kr][wn + nt * 8 + ms];
                b[nt][1] = Bs[kr + 4][wn + nt * 8 + ms];
            }
#pragma unroll
            for (int mt = 0; mt < 4; mt++)
#pragma unroll
                for (int nt = 0; nt < 8; nt++)
                    mma8(acc[mt][nt], a[mt], b[nt]);
        }
        if (more) { __syncthreads(); STORE(); __syncthreads(); }
    }
#undef GL
#undef STORE

#pragma unroll
    for (int mt = 0; mt < 4; mt++) {
        int r0 = bm + wm + mt * 16 + (lane >> 2);
#pragma unroll
        for (int nt = 0; nt < 8; nt++) {
            int c0 = bn + wn + nt * 8 + (lane & 3) * 2;
            *(float2*)&C[(size_t)r0 * N + c0]       = make_float2(acc[mt][nt][0], acc[mt][nt][1]);
            *(float2*)&C[(size_t)(r0 + 8) * N + c0] = make_float2(acc[mt][nt][2], acc[mt][nt][3]);
        }
    }
}

// ---------------------------------------------------------------------------
// Shared NT-GEMM body for pos/score: C(128x128) = (Arow + bias) @ Brow^T, K=64.
// Both operands row-major with contiguous K (transposed scalar stores).
// ---------------------------------------------------------------------------
#define NT_GL(k0) do {                                               \
        sa[0] = *(const float4*)(arow + (k0));                       \
        sa[1] = *(const float4*)(arow + (k0) + 4);                   \
        sa[2] = *(const float4*)(arow + (k0) + 8);                   \
        sa[3] = *(const float4*)(arow + (k0) + 12);                  \
        sv[0] = *(const float4*)(vrow + (k0));                       \
        sv[1] = *(const float4*)(vrow + (k0) + 4);                   \
        sv[2] = *(const float4*)(vrow + (k0) + 8);                   \
        sv[3] = *(const float4*)(vrow + (k0) + 12);                  \
        sb[0] = *(const float4*)(brow + (k0));                       \
        sb[1] = *(const float4*)(brow + (k0) + 4);                   \
        sb[2] = *(const float4*)(brow + (k0) + 8);                   \
        sb[3] = *(const float4*)(brow + (k0) + 12);                  \
    } while (0)
#define NT_STORE() do {                                                          \
        _Pragma("unroll")                                                        \
        for (int i = 0; i < 4; i++) {                                            \
            As[i*4+0][tid] = tf32r(((const float*)&sa[i])[0] + ((const float*)&sv[i])[0]); \
            As[i*4+1][tid] = tf32r(((const float*)&sa[i])[1] + ((const float*)&sv[i])[1]); \
            As[i*4+2][tid] = tf32r(((const float*)&sa[i])[2] + ((const float*)&sv[i])[2]); \
            As[i*4+3][tid] = tf32r(((const float*)&sa[i])[3] + ((const float*)&sv[i])[3]); \
            Bs[i*4+0][tid] = tf32r(((const float*)&sb[i])[0]);                   \
            Bs[i*4+1][tid] = tf32r(((const float*)&sb[i])[1]);                   \
            Bs[i*4+2][tid] = tf32r(((const float*)&sb[i])[2]);                   \
            Bs[i*4+3][tid] = tf32r(((const float*)&sb[i])[3]);                   \
        }                                                                        \
    } while (0)
#define NT_MAINLOOP()                                                  \
    NT_GL(0); NT_STORE(); __syncthreads();                             \
    _Pragma("unroll")                                                  \
    for (int k0 = 0; k0 < HDIM; k0 += 16) {                            \
        const bool more = (k0 + 16 < HDIM);                            \
        if (more) NT_GL(k0 + 16);                                      \
        _Pragma("unroll")                                              \
        for (int kk = 0; kk < 16; kk += 8) {                           \
            const int kr = kk + (lane & 3);                            \
            const int ms = lane >> 2;                                  \
            float a[4][4], b[8][2];                                    \
            _Pragma("unroll")                                          \
            for (int mt = 0; mt < 4; mt++) {                           \
                a[mt][0] = As[kr][wm + mt * 16 + ms];                  \
                a[mt][1] = As[kr][wm + mt * 16 + ms + 8];              \
                a[mt][2] = As[kr + 4][wm + mt * 16 + ms];              \
                a[mt][3] = As[kr + 4][wm + mt * 16 + ms + 8];          \
            }                                                          \
            _Pragma("unroll")                                          \
            for (int nt = 0; nt < 8; nt++) {                           \
                b[nt][0] = Bs[kr][wn + nt * 8 + ms];                   \
                b[nt][1] = Bs[kr + 4][wn + nt * 8 + ms];               \
            }                                                          \
            _Pragma("unroll")                                          \
            for (int mt = 0; mt < 4; mt++)                             \
                _Pragma("unroll")                                      \
                for (int nt = 0; nt < 8; nt++)                         \
                    mma8(acc[mt][nt], a[mt], b[nt]);                   \
        }                                                              \
        if (more) { __syncthreads(); NT_STORE(); __syncthreads(); }    \
    }

// ---------------------------------------------------------------------------
// P[h][L][jj] = sum_d (q[L,h,d]+v[h,d]) * p[jj,h,d]   (NT, K=64)
// ---------------------------------------------------------------------------
__global__ void __launch_bounds__(128) pos_gemm_tf32(
    const float* __restrict__ q, const float* __restrict__ p,
    const float* __restrict__ vb, float* __restrict__ P)
{
    __shared__ float As[16][136];
    __shared__ float Bs[16][136];
    const int tid  = threadIdx.x;
    const int lane = tid & 31;
    const int w    = tid >> 5;
    const int wm   = (w >> 1) * 64;
    const int wn   = (w & 1) * 64;
    const int h    = blockIdx.z;
    const int L0   = blockIdx.y * 128;
    const int j0   = blockIdx.x * 128;

    const float* arow = q  + (size_t)(L0 + tid) * HD + h * HDIM;
    const float* vrow = vb + h * HDIM;
    const float* brow = p  + (size_t)(j0 + tid) * HD + h * HDIM;

    float acc[4][8][4] = {};
    float4 sa[4], sv[4], sb[4];
    NT_MAINLOOP();

#pragma unroll
    for (int mt = 0; mt < 4; mt++) {
        int r0 = L0 + wm + mt * 16 + (lane >> 2);
#pragma unroll
        for (int nt = 0; nt < 8; nt++) {
            int c0 = j0 + wn + nt * 8 + (lane & 3) * 2;
            float* o = P + ((size_t)h * LQG + r0) * TT + c0;
            *(float2*)o            = make_float2(acc[mt][nt][0], acc[mt][nt][1]);
            *(float2*)(o + 8 * TT) = make_float2(acc[mt][nt][2], acc[mt][nt][3]);
        }
    }
}

// ---------------------------------------------------------------------------
// rel_shift gather: pos(b,i,j) with L = b*CS+i
// ---------------------------------------------------------------------------
__device__ __forceinline__ float pos_val(const float* __restrict__ Pm,
                                         int h, int L, int jj)
{
    int s  = jj + LQG - L;
    int n  = (s > TT) + (s > 2 * TT + 1);
    int jp = s - n * (TT + 1);
    int Lp = L + n;
    float pos = 0.f;
    if (jp > 0 && Lp < LQG)
        pos = Pm[((size_t)h * LQG + Lp) * TT + (jp - 1)];
    return pos;
}

// ---------------------------------------------------------------------------
// Scores: S[b,h,i,j] = (q+u)·k + rel_shift(P), masked. Block 128x128, K=64.
// Fully-masked tiles (j0 > i0+127+PS) skip the GEMM entirely.
// ---------------------------------------------------------------------------
__global__ void __launch_bounds__(128) score_gemm_tf32(
    const float* __restrict__ q, const float* __restrict__ kv,
    const float* __restrict__ ub, const float* __restrict__ Pm,
    float* __restrict__ S)
{
    __shared__ float As[16][136];
    __shared__ float Bs[16][136];
    const int tid  = threadIdx.x;
    const int lane = tid & 31;
    const int w    = tid >> 5;
    const int wm   = (w >> 1) * 64;
    const int wn   = (w & 1) * 64;
    const int bh   = blockIdx.z;
    const int b    = bh >> 4;
    const int h    = bh & 15;
    const int i0   = blockIdx.y * 128;
    const int j0   = blockIdx.x * 128;

    if (j0 > i0 + 127 + PSQ) {
        // whole tile masked: write -1e30 and exit (no GEMM work)
#pragma unroll
        for (int mt = 0; mt < 4; mt++) {
            int ii = i0 + wm + mt * 16 + (lane >> 2);
#pragma unroll
            for (int nt = 0; nt < 8; nt++) {
                int jj0 = j0 + wn + nt * 8 + (lane & 3) * 2;
                float* so0 = S + ((size_t)(b * NH + h) * CSQ + ii) * TT + jj0;
                *(float2*)so0            = make_float2(-1e30f, -1e30f);
                *(float2*)(so0 + 8 * TT) = make_float2(-1e30f, -1e30f);
            }
        }
        return;
    }

    const float* arow = q  + (size_t)(b * CSQ + i0 + tid) * HD + h * HDIM;
    const float* vrow = ub + h * HDIM;
    const float* brow = kv + ((size_t)b * TT + j0 + tid) * (2 * HD) + h * HDIM;

    float acc[4][8][4] = {};
    float4 sa[4], sv[4], sb[4];
    NT_MAINLOOP();

#pragma unroll
    for (int mt = 0; mt < 4; mt++) {
        int ii_base = i0 + wm + mt * 16 + (lane >> 2);
#pragma unroll
        for (int nt = 0; nt < 8; nt++) {
            int jj0 = j0 + wn + nt * 8 + (lane & 3) * 2;
#pragma unroll
            for (int rr = 0; rr < 2; rr++) {
                int ii = ii_base + rr * 8;
                int L  = b * CSQ + ii;
                float v0, v1;
                if (jj0 > ii + PSQ)       v0 = -1e30f;
                else                      v0 = acc[mt][nt][rr * 2 + 0] + pos_val(Pm, h, L, jj0);
                if (jj0 + 1 > ii + PSQ)   v1 = -1e30f;
                else                      v1 = acc[mt][nt][rr * 2 + 1] + pos_val(Pm, h, L, jj0 + 1);
                float* so = S + ((size_t)(b * NH + h) * CSQ + ii) * TT + jj0;
                *(float2*)so = make_float2(v0, v1);
            }
        }
    }
}

// ---------------------------------------------------------------------------
// Row softmax over j (T=2048) of SCALE*score, in place. 1 block per row.
// ---------------------------------------------------------------------------
__global__ void __launch_bounds__(256) softmax_k(float* __restrict__ S)
{
    const int t = threadIdx.x;
    float4* x = (float4*)(S + (size_t)blockIdx.x * TT);
    float4 v0 = x[t];
    float4 v1 = x[t + 256];

    float m = fmaxf(fmaxf(fmaxf(v0.x, v0.y), fmaxf(v0.z, v0.w)),
                    fmaxf(fmaxf(v1.x, v1.y), fmaxf(v1.z, v1.w)));
#pragma unroll
    for (int o = 16; o > 0; o >>= 1)
        m = fmaxf(m, __shfl_xor_sync(0xffffffffu, m, o));
    __shared__ float red[8];
    if ((t & 31) == 0) red[t >> 5] = m;
    __syncthreads();
    float bm = red[0];
#pragma unroll
    for (int w = 1; w < 8; w++) bm = fmaxf(bm, red[w]);

    v0.x = __expf((v0.x - bm) * SCALE);  v0.y = __expf((v0.y - bm) * SCALE);
    v0.z = __expf((v0.z - bm) * SCALE);  v0.w = __expf((v0.w - bm) * SCALE);
    v1.x = __expf((v1.x - bm) * SCALE);  v1.y = __expf((v1.y - bm) * SCALE);
    v1.z = __expf((v1.z - bm) * SCALE);  v1.w = __expf((v1.w - bm) * SCALE);
    float s = v0.x + v0.y + v0.z + v0.w + v1.x + v1.y + v1.z + v1.w;
#pragma unroll
    for (int o = 16; o > 0; o >>= 1)
        s += __shfl_xor_sync(0xffffffffu, s, o);
    __syncthreads();
    if ((t & 31) == 0) red[t >> 5] = s;
    __syncthreads();
    float tot = 0.f;
#pragma unroll
    for (int w = 0; w < 8; w++) tot += red[w];
    float inv = 1.0f / tot;
    v0.x *= inv; v0.y *= inv; v0.z *= inv; v0.w *= inv;
    v1.x *= inv; v1.y *= inv; v1.z *= inv; v1.w *= inv;
    x[t]       = v0;
    x[t + 256] = v1;
}

// ---------------------------------------------------------------------------
// ao[b,i,h,:] = sum_j S[b,h,i,j] * v[b,j,h,:]
// Block 128x64; 4 warps in 2(m) x 2(n); warp 64x32 = 4x4 m16n8 tiles.
// K truncated by causality.
// ---------------------------------------------------------------------------
__global__ void __launch_bounds__(128) awv_gemm_tf32(
    const float* __restrict__ S, const float* __restrict__ kv,
    float* __restrict__ ao)
{
    __shared__ float As[16][136];
    __shared__ float Bs[16][72];
    const int tid  = threadIdx.x;
    const int lane = tid & 31;
    const int w    = tid >> 5;
    const int wm   = (w >> 1) * 64;
    const int wn   = (w & 1) * 32;
    const int bh   = blockIdx.z;
    const int b    = bh >> 4;
    const int h    = bh & 15;
    const int i0   = blockIdx.y * 128;

    const float* arow = S + ((size_t)(b * NH + h) * CSQ + i0 + tid) * TT;
    const int br = tid >> 3;
    const int cq = tid & 7;
    const float* bp = kv + ((size_t)b * TT + br) * (2 * HD) + HD + h * HDIM + cq * 4;

    float acc[4][4][4] = {};
    const int Kef = min(TT, i0 + 128 + PSQ);
    float4 sa[4], sb[2];

#define AGL(k0) do {                                                 \
        sa[0] = *(const float4*)(arow + (k0));                       \
        sa[1] = *(const float4*)(arow + (k0) + 4);                   \
        sa[2] = *(const float4*)(arow + (k0) + 8);                   \
        sa[3] = *(const float4*)(arow + (k0) + 12);                  \
        sb[0] = *(const float4*)(bp + (size_t)(k0) * (2 * HD));      \
        sb[1] = *(const float4*)(bp + (size_t)(k0) * (2 * HD) + 32); \
    } while (0)
#define ASTORE() do {                                                \
        As[0][tid]  = tf32r(sa[0].x); As[1][tid]  = tf32r(sa[0].y);  \
        As[2][tid]  = tf32r(sa[0].z); As[3][tid]  = tf32r(sa[0].w);  \
        As[4][tid]  = tf32r(sa[1].x); As[5][tid]  = tf32r(sa[1].y);  \
        As[6][tid]  = tf32r(sa[1].z); As[7][tid]  = tf32r(sa[1].w);  \
        As[8][tid]  = tf32r(sa[2].x); As[9][tid]  = tf32r(sa[2].y);  \
        As[10][tid] = tf32r(sa[2].z); As[11][tid] = tf32r(sa[2].w);  \
        As[12][tid] = tf32r(sa[3].x); As[13][tid] = tf32r(sa[3].y);  \
        As[14][tid] = tf32r(sa[3].z); As[15][tid] = tf32r(sa[3].w);  \
        *(float4*)&Bs[br][cq * 4]      = tf32r4(sb[0]);              \
        *(float4*)&Bs[br][cq * 4 + 32] = tf32r4(sb[1]);              \
    } while (0)

    AGL(0); ASTORE(); __syncthreads();
    for (int k0 = 0; k0 < Kef; k0 += 16) {
        const bool more = (k0 + 16 < Kef);
        if (more) AGL(k0 + 16);
#pragma unroll
        for (int kk = 0; kk < 16; kk += 8) {
            const int kr = kk + (lane & 3);
            const int ms = lane >> 2;
            float a[4][4], bq[4][2];
#pragma unroll
            for (int mt = 0; mt < 4; mt++) {
                a[mt][0] = As[kr][wm + mt * 16 + ms];
                a[mt][1] = As[kr][wm + mt * 16 + ms + 8];
                a[mt][2] = As[kr + 4][wm + mt * 16 + ms];
                a[mt][3] = As[kr + 4][wm + mt * 16 + ms + 8];
            }
#pragma unroll
            for (int nt = 0; nt < 4; nt++) {
                bq[nt][0] = Bs[kr][wn + nt * 8 + ms];
                bq[nt][1] = Bs[kr + 4][wn + nt * 8 + ms];
            }
#pragma unroll
            for (int mt = 0; mt < 4; mt++)
#pragma unroll
                for (int nt = 0; nt < 4; nt++)
                    mma8(acc[mt][nt], a[mt], bq[nt]);
        }
        if (more) { __syncthreads(); ASTORE(); __syncthreads(); }
    }
#undef AGL
#undef ASTORE

#pragma unroll
    for (int mt = 0; mt < 4; mt++) {
        int r0 = i0 + wm + mt * 16 + (lane >> 2);
#pragma unroll
        for (int nt = 0; nt < 4; nt++) {
            int c0 = wn + nt * 8 + (lane & 3) * 2;
            float* o = ao + (size_t)(b * CSQ + r0) * HD + h * HDIM + c0;
            *(float2*)o            = make_float2(acc[mt][nt][0], acc[mt][nt][1]);
            *(float2*)(o + 8 * HD) = make_float2(acc[mt][nt][2], acc[mt][nt][3]);
        }
    }
}

// ---------------------------------------------------------------------------
// Launch: 8 kernels, default stream, graph-capturable.
// Inputs: input_, pos_embs, memory, u, v, W_kv, W_q, W_p, W_out, mask(unused).
// ---------------------------------------------------------------------------
extern "C" void kernel_launch(void* const* d_in, const int* in_sizes, int n_in,
                              void* d_out, int out_size)
{
    const float* input_ = (const float*)d_in[0];
    const float* pos    = (const float*)d_in[1];
    const float* memory = (const float*)d_in[2];
    const float* u      = (const float*)d_in[3];
    const float* v      = (const float*)d_in[4];
    const float* W_kv   = (const float*)d_in[5];
    const float* W_q    = (const float*)d_in[6];
    const float* W_p    = (const float*)d_in[7];
    const float* W_out  = (const float*)d_in[8];
    float* out = (float*)d_out;

    float *qb, *kvb, *pb, *Pb, *Sb, *aob;
    cudaGetSymbolAddress((void**)&qb,  g_q);
    cudaGetSymbolAddress((void**)&kvb, g_kv);
    cudaGetSymbolAddress((void**)&pb,  g_p);
    cudaGetSymbolAddress((void**)&Pb,  g_P);
    cudaGetSymbolAddress((void**)&Sb,  g_S);
    cudaGetSymbolAddress((void**)&aob, g_ao);

    dim3 thr(128);

    // q = input_ @ W_q                      (4096 x 1024 x 1024)
    gemm_tf32<0><<<dim3(HD / 128, LQG / 128), thr>>>(input_, nullptr, W_q, qb, LQG, HD, DIN);
    // kv = concat(memory, input_) @ W_kv    (8192 x 2048 x 1024)
    gemm_tf32<1><<<dim3(2 * HD / 128, (BSZ * TT) / 128), thr>>>(memory, input_, W_kv, kvb, BSZ * TT, 2 * HD, DIN);
    // p = pos_embs @ W_p                    (2048 x 1024 x 1024)
    gemm_tf32<0><<<dim3(HD / 128, TT / 128), thr>>>(pos, nullptr, W_p, pb, TT, HD, DIN);
    // P[h] = (q + v) @ p^T per head         (16 x 4096 x 2048 x 64)
    pos_gemm_tf32<<<dim3(TT / 128, LQG / 128, NH), thr>>>(qb, pb, v, Pb);
    // scores + rel-shift gather + mask
    score_gemm_tf32<<<dim3(TT / 128, CSQ / 128, BSZ * NH), thr>>>(qb, kvb, u, Pb, Sb);
    // softmax
    softmax_k<<<BSZ * NH * CSQ, 256>>>(Sb);
    // attn @ V
    awv_gemm_tf32<<<dim3(1, CSQ / 128, BSZ * NH), thr>>>(Sb, kvb, aob);
    // out = ao @ W_out                      (4096 x 1024 x 1024)
    gemm_tf32<0><<<dim3(DIN / 128, LQG / 128), thr>>>(aob, nullptr, W_out, out, LQG, DIN, HD);
}

// round 8
// speedup vs baseline: 1.6358x; 1.2721x over previous
#include <cuda_runtime.h>

// Problem constants
#define BSZ   4
#define CSQ   1024
#define PSQ   1024
#define DIN   1024
#define NH    16
#define HDIM  64
#define TT    2048        // T = CS + PS
#define LQG   4096        // BSZ*CSQ global query rows
#define HD    1024        // NH*HDIM
#define SCALE 0.125f      // 1/sqrt(64)

// ---------------------------------------------------------------------------
// Scratch (device globals; no dynamic allocation allowed)
// ---------------------------------------------------------------------------
__device__ float g_q [(size_t)LQG * HD];                 //  16.8 MB  q_tfmd
__device__ float g_kv[(size_t)BSZ * TT * 2 * HD];        //  67 MB    [k | v]
__device__ float g_p [(size_t)TT * HD];                  //   8.4 MB  p_tfmd
__device__ float g_P [(size_t)NH * LQG * TT];            // 512 MB    (q+v)@p^T per head
__device__ float g_ao[(size_t)LQG * HD];                 //  16.8 MB  attn output (pre W_out)

// ---------------------------------------------------------------------------
// tf32 helpers
// ---------------------------------------------------------------------------
__device__ __forceinline__ float tf32r(float x) {
    float y;
    asm("cvt.rna.tf32.f32 %0, %1;" : "=f"(y) : "f"(x));
    return y;
}
__device__ __forceinline__ float4 tf32r4(float4 v) {
    return make_float4(tf32r(v.x), tf32r(v.y), tf32r(v.z), tf32r(v.w));
}

// D += A(16x8 row) * B(8x8 col)
__device__ __forceinline__ void mma8(float* d, const float* a, const float* b) {
    asm volatile(
        "mma.sync.aligned.m16n8k8.row.col.f32.tf32.tf32.f32 "
        "{%0,%1,%2,%3}, {%4,%5,%6,%7}, {%8,%9}, {%0,%1,%2,%3};"
        : "+f"(d[0]), "+f"(d[1]), "+f"(d[2]), "+f"(d[3])
        : "r"(__float_as_uint(a[0])), "r"(__float_as_uint(a[1])),
          "r"(__float_as_uint(a[2])), "r"(__float_as_uint(a[3])),
          "r"(__float_as_uint(b[0])), "r"(__float_as_uint(b[1])));
}

// ---------------------------------------------------------------------------
// Generic 128x128 tf32 GEMM, row-major A(MxK) * B(KxN) -> C(MxN), K%16==0.
// MODE 0: A plain. MODE 1: A rows = virtual concat(memory, input_) over seq.
// 128 threads = 4 warps in 2(m) x 2(n); warp tile 64x64 = 4x8 m16n8 tiles.
// ---------------------------------------------------------------------------
template <int MODE>
__global__ void __launch_bounds__(128) gemm_tf32(
    const float* __restrict__ A, const float* __restrict__ A2,
    const float* __restrict__ B, float* __restrict__ C,
    int M, int N, int K)
{
    __shared__ float As[16][136];
    __shared__ float Bs[16][136];
    const int tid  = threadIdx.x;
    const int lane = tid & 31;
    const int w    = tid >> 5;
    const int wm   = (w >> 1) * 64;
    const int wn   = (w & 1) * 64;
    const int bm   = blockIdx.y * 128;
    const int bn   = blockIdx.x * 128;

    const float* arow;
    if (MODE == 0) {
        arow = A + (size_t)(bm + tid) * K;
    } else {
        int row = bm + tid;
        int b   = row / TT;
        int r   = row - b * TT;
        arow = (r < PSQ) ? A  + (size_t)(b * PSQ + r)         * K
                         : A2 + (size_t)(b * CSQ + (r - PSQ)) * K;
    }
    const int br = tid >> 3;
    const int cq = tid & 7;
    const float* bp = B + (size_t)br * N + bn + cq * 4;

    float acc[4][8][4] = {};
    float4 sa[4], sb[4];

#define GL(k0) do {                                                  \
        sa[0] = *(const float4*)(arow + (k0));                       \
        sa[1] = *(const float4*)(arow + (k0) + 4);                   \
        sa[2] = *(const float4*)(arow + (k0) + 8);                   \
        sa[3] = *(const float4*)(arow + (k0) + 12);                  \
        sb[0] = *(const float4*)(bp + (size_t)(k0) * N);             \
        sb[1] = *(const float4*)(bp + (size_t)(k0) * N + 32);        \
        sb[2] = *(const float4*)(bp + (size_t)(k0) * N + 64);        \
        sb[3] = *(const float4*)(bp + (size_t)(k0) * N + 96);       \
    } while (0)
#define STORE() do {                                                 \
        As[0][tid]  = tf32r(sa[0].x); As[1][tid]  = tf32r(sa[0].y);  \
        As[2][tid]  = tf32r(sa[0].z); As[3][tid]  = tf32r(sa[0].w);  \
        As[4][tid]  = tf32r(sa[1].x); As[5][tid]  = tf32r(sa[1].y);  \
        As[6][tid]  = tf32r(sa[1].z); As[7][tid]  = tf32r(sa[1].w);  \
        As[8][tid]  = tf32r(sa[2].x); As[9][tid]  = tf32r(sa[2].y);  \
        As[10][tid] = tf32r(sa[2].z); As[11][tid] = tf32r(sa[2].w);  \
        As[12][tid] = tf32r(sa[3].x); As[13][tid] = tf32r(sa[3].y);  \
        As[14][tid] = tf32r(sa[3].z); As[15][tid] = tf32r(sa[3].w);  \
        *(float4*)&Bs[br][cq * 4]      = tf32r4(sb[0]);              \
        *(float4*)&Bs[br][cq * 4 + 32] = tf32r4(sb[1]);              \
        *(float4*)&Bs[br][cq * 4 + 64] = tf32r4(sb[2]);              \
        *(float4*)&Bs[br][cq * 4 + 96] = tf32r4(sb[3]);              \
    } while (0)

    GL(0); STORE(); __syncthreads();
    for (int k0 = 0; k0 < K; k0 += 16) {
        const bool more = (k0 + 16 < K);
        if (more) GL(k0 + 16);
#pragma unroll
        for (int kk = 0; kk < 16; kk += 8) {
            const int kr = kk + (lane & 3);
            const int ms = lane >> 2;
            float a[4][4], b[8][2];
#pragma unroll
            for (int mt = 0; mt < 4; mt++) {
                a[mt][0] = As[kr][wm + mt * 16 + ms];
                a[mt][1] = As[kr][wm + mt * 16 + ms + 8];
                a[mt][2] = As[kr + 4][wm + mt * 16 + ms];
                a[mt][3] = As[kr + 4][wm + mt * 16 + ms + 8];
            }
#pragma unroll
            for (int nt = 0; nt < 8; nt++) {
                b[nt][0] = Bs[kr][wn + nt * 8 + ms];
                b[nt][1] = Bs[kr + 4][wn + nt * 8 + ms];
            }
#pragma unroll
            for (int mt = 0; mt < 4; mt++)
#pragma unroll
                for (int nt = 0; nt < 8; nt++)
                    mma8(acc[mt][nt], a[mt], b[nt]);
        }
        if (more) { __syncthreads(); STORE(); __syncthreads(); }
    }
#undef GL
#undef STORE

#pragma unroll
    for (int mt = 0; mt < 4; mt++) {
        int r0 = bm + wm + mt * 16 + (lane >> 2);
#pragma unroll
        for (int nt = 0; nt < 8; nt++) {
            int c0 = bn + wn + nt * 8 + (lane & 3) * 2;
            *(float2*)&C[(size_t)r0 * N + c0]       = make_float2(acc[mt][nt][0], acc[mt][nt][1]);
            *(float2*)&C[(size_t)(r0 + 8) * N + c0] = make_float2(acc[mt][nt][2], acc[mt][nt][3]);
        }
    }
}

// ---------------------------------------------------------------------------
// P[h][L][jj] = sum_d (q[L,h,d]+v[h,d]) * p[jj,h,d]   (NT, K=64)
// ---------------------------------------------------------------------------
__global__ void __launch_bounds__(128) pos_gemm_tf32(
    const float* __restrict__ q, const float* __restrict__ p,
    const float* __restrict__ vb, float* __restrict__ P)
{
    __shared__ float As[16][136];
    __shared__ float Bs[16][136];
    const int tid  = threadIdx.x;
    const int lane = tid & 31;
    const int w    = tid >> 5;
    const int wm   = (w >> 1) * 64;
    const int wn   = (w & 1) * 64;
    const int h    = blockIdx.z;
    const int L0   = blockIdx.y * 128;
    const int j0   = blockIdx.x * 128;

    const float* arow = q  + (size_t)(L0 + tid) * HD + h * HDIM;
    const float* vrow = vb + h * HDIM;
    const float* brow = p  + (size_t)(j0 + tid) * HD + h * HDIM;

    float acc[4][8][4] = {};
    float4 sa[4], sv[4], sb[4];

#define NT_GL(k0) do {                                               \
        sa[0] = *(const float4*)(arow + (k0));                       \
        sa[1] = *(const float4*)(arow + (k0) + 4);                   \
        sa[2] = *(const float4*)(arow + (k0) + 8);                   \
        sa[3] = *(const float4*)(arow + (k0) + 12);                  \
        sv[0] = *(const float4*)(vrow + (k0));                       \
        sv[1] = *(const float4*)(vrow + (k0) + 4);                   \
        sv[2] = *(const float4*)(vrow + (k0) + 8);                   \
        sv[3] = *(const float4*)(vrow + (k0) + 12);                  \
        sb[0] = *(const float4*)(brow + (k0));                       \
        sb[1] = *(const float4*)(brow + (k0) + 4);                   \
        sb[2] = *(const float4*)(brow + (k0) + 8);                   \
        sb[3] = *(const float4*)(brow + (k0) + 12);                  \
    } while (0)
#define NT_STORE() do {                                                          \
        _Pragma("unroll")                                                        \
        for (int i = 0; i < 4; i++) {                                            \
            As[i*4+0][tid] = tf32r(((const float*)&sa[i])[0] + ((const float*)&sv[i])[0]); \
            As[i*4+1][tid] = tf32r(((const float*)&sa[i])[1] + ((const float*)&sv[i])[1]); \
            As[i*4+2][tid] = tf32r(((const float*)&sa[i])[2] + ((const float*)&sv[i])[2]); \
            As[i*4+3][tid] = tf32r(((const float*)&sa[i])[3] + ((const float*)&sv[i])[3]); \
            Bs[i*4+0][tid] = tf32r(((const float*)&sb[i])[0]);                   \
            Bs[i*4+1][tid] = tf32r(((const float*)&sb[i])[1]);                   \
            Bs[i*4+2][tid] = tf32r(((const float*)&sb[i])[2]);                   \
            Bs[i*4+3][tid] = tf32r(((const float*)&sb[i])[3]);                   \
        }                                                                        \
    } while (0)

    NT_GL(0); NT_STORE(); __syncthreads();
#pragma unroll
    for (int k0 = 0; k0 < HDIM; k0 += 16) {
        const bool more = (k0 + 16 < HDIM);
        if (more) NT_GL(k0 + 16);
#pragma unroll
        for (int kk = 0; kk < 16; kk += 8) {
            const int kr = kk + (lane & 3);
            const int ms = lane >> 2;
            float a[4][4], b[8][2];
#pragma unroll
            for (int mt = 0; mt < 4; mt++) {
                a[mt][0] = As[kr][wm + mt * 16 + ms];
                a[mt][1] = As[kr][wm + mt * 16 + ms + 8];
                a[mt][2] = As[kr + 4][wm + mt * 16 + ms];
                a[mt][3] = As[kr + 4][wm + mt * 16 + ms + 8];
            }
#pragma unroll
            for (int nt = 0; nt < 8; nt++) {
                b[nt][0] = Bs[kr][wn + nt * 8 + ms];
                b[nt][1] = Bs[kr + 4][wn + nt * 8 + ms];
            }
#pragma unroll
            for (int mt = 0; mt < 4; mt++)
#pragma unroll
                for (int nt = 0; nt < 8; nt++)
                    mma8(acc[mt][nt], a[mt], b[nt]);
        }
        if (more) { __syncthreads(); NT_STORE(); __syncthreads(); }
    }
#undef NT_GL
#undef NT_STORE

#pragma unroll
    for (int mt = 0; mt < 4; mt++) {
        int r0 = L0 + wm + mt * 16 + (lane >> 2);
#pragma unroll
        for (int nt = 0; nt < 8; nt++) {
            int c0 = j0 + wn + nt * 8 + (lane & 3) * 2;
            float* o = P + ((size_t)h * LQG + r0) * TT + c0;
            *(float2*)o            = make_float2(acc[mt][nt][0], acc[mt][nt][1]);
            *(float2*)(o + 8 * TT) = make_float2(acc[mt][nt][2], acc[mt][nt][3]);
        }
    }
}

// ---------------------------------------------------------------------------
// rel_shift gather: pos(b,i,j) with L = b*CS+i
// ---------------------------------------------------------------------------
__device__ __forceinline__ float pos_val(const float* __restrict__ Pm,
                                         int h, int L, int jj)
{
    int s  = jj + LQG - L;
    int n  = (s > TT) + (s > 2 * TT + 1);
    int jp = s - n * (TT + 1);
    int Lp = L + n;
    float pos = 0.f;
    if (jp > 0 && Lp < LQG)
        pos = Pm[((size_t)h * LQG + Lp) * TT + (jp - 1)];
    return pos;
}

// ---------------------------------------------------------------------------
// Fused attention: scores (+pos gather, mask, scale) -> online softmax -> P@V.
// One CTA = 128 query rows of one (b,h). 256 threads = 8 warps; warp w owns
// rows [i0+16w, i0+16w+16) completely (m16 x n64 score tiles), so softmax row
// reductions are quad shuffles. (q+u) A-fragments persist in registers.
// probs round-trip through SMEM (k-major) to become awv A-fragments.
// SMEM: Sp (q staging, then probs) [64][136] | Bk [64][72] | Bv [64][72].
// ---------------------------------------------------------------------------
#define ATT_SMEM ((64 * 136 + 64 * 72 + 64 * 72) * 4)

__global__ void __launch_bounds__(256) attn_fused(
    const float* __restrict__ q, const float* __restrict__ kv,
    const float* __restrict__ ub, const float* __restrict__ Pm,
    float* __restrict__ ao)
{
    extern __shared__ float dyn[];
    float (*Sp)[136] = (float(*)[136])dyn;
    float (*Bk)[72]  = (float(*)[72])(dyn + 64 * 136);
    float (*Bv)[72]  = (float(*)[72])(dyn + 64 * 136 + 64 * 72);

    const int tid  = threadIdx.x;
    const int lane = tid & 31;
    const int w    = tid >> 5;
    const int wm   = w * 16;
    const int bh   = blockIdx.y;
    const int b    = bh >> 4;
    const int h    = bh & 15;
    const int i0   = blockIdx.x * 128;
    const int r    = lane >> 2;     // fragment row within m16 (0..7)
    const int kb   = lane & 3;      // fragment k/col quad index

    // ---- stage (q+u) k-major into Sp, preload persistent A-fragments ----
    {
        int row = tid >> 1;
        int kq  = (tid & 1) * 32;
        const float* qr = q  + (size_t)(b * CSQ + i0 + row) * HD + h * HDIM + kq;
        const float* ur = ub + h * HDIM + kq;
#pragma unroll
        for (int i = 0; i < 8; i++) {
            float4 a  = *(const float4*)(qr + i * 4);
            float4 uu = *(const float4*)(ur + i * 4);
            Sp[kq + i * 4 + 0][row] = tf32r(a.x + uu.x);
            Sp[kq + i * 4 + 1][row] = tf32r(a.y + uu.y);
            Sp[kq + i * 4 + 2][row] = tf32r(a.z + uu.z);
            Sp[kq + i * 4 + 3][row] = tf32r(a.w + uu.w);
        }
    }
    __syncthreads();
    float aq[8][4];
#pragma unroll
    for (int ks = 0; ks < 8; ks++) {
        aq[ks][0] = Sp[ks * 8 + kb][wm + r];
        aq[ks][1] = Sp[ks * 8 + kb][wm + r + 8];
        aq[ks][2] = Sp[ks * 8 + kb + 4][wm + r];
        aq[ks][3] = Sp[ks * 8 + kb + 4][wm + r + 8];
    }
    __syncthreads();   // Sp now free for probs

    float m0 = -3.0e38f, m1 = -3.0e38f, l0 = 0.f, l1 = 0.f;
    float acc_o[8][4] = {};

    const int row0 = i0 + wm + r;        // global query row (set 0; set 1 = +8)
    const int Lr   = b * CSQ + row0;
    const int Kef  = min(TT, i0 + 128 + PSQ);

    for (int j0 = 0; j0 < Kef; j0 += 64) {
        // ---- load k tile (transposed, tf32) and v tile (direct, tf32) ----
        {
            int j  = tid & 63;
            int dq = (tid >> 6) * 16;
            const float* kr_ = kv + ((size_t)(b * TT + j0 + j)) * (2 * HD) + h * HDIM + dq;
#pragma unroll
            for (int i = 0; i < 4; i++) {
                float4 kx = *(const float4*)(kr_ + i * 4);
                Bk[dq + i * 4 + 0][j] = tf32r(kx.x);
                Bk[dq + i * 4 + 1][j] = tf32r(kx.y);
                Bk[dq + i * 4 + 2][j] = tf32r(kx.z);
                Bk[dq + i * 4 + 3][j] = tf32r(kx.w);
            }
            const float* vr_ = kr_ + HD;
#pragma unroll
            for (int i = 0; i < 4; i++) {
                float4 vx = *(const float4*)(vr_ + i * 4);
                *(float4*)&Bv[j][dq + i * 4] = tf32r4(vx);
            }
        }
        __syncthreads();

        // ---- score GEMM: warp computes 16 x 64 ----
        float s[8][4] = {};
#pragma unroll
        for (int ks = 0; ks < 8; ks++) {
            float bq[8][2];
#pragma unroll
            for (int nt = 0; nt < 8; nt++) {
                bq[nt][0] = Bk[ks * 8 + kb][nt * 8 + r];
                bq[nt][1] = Bk[ks * 8 + kb + 4][nt * 8 + r];
            }
#pragma unroll
            for (int nt = 0; nt < 8; nt++)
                mma8(s[nt], aq[ks], bq[nt]);
        }

        // ---- epilogue: pos gather + mask + scale ----
#pragma unroll
        for (int nt = 0; nt < 8; nt++) {
            int jjb = j0 + nt * 8 + 2 * kb;
#pragma unroll
            for (int cc = 0; cc < 2; cc++) {
                int jj = jjb + cc;
                s[nt][cc]     = (jj > row0 + PSQ)     ? -1e30f
                              : (s[nt][cc]     + pos_val(Pm, h, Lr, jj))     * SCALE;
                s[nt][2 + cc] = (jj > row0 + 8 + PSQ) ? -1e30f
                              : (s[nt][2 + cc] + pos_val(Pm, h, Lr + 8, jj)) * SCALE;
            }
        }

        // ---- online softmax update (rows are quad-local) ----
        float tm0 = -3.0e38f, tm1 = -3.0e38f;
#pragma unroll
        for (int nt = 0; nt < 8; nt++) {
            tm0 = fmaxf(tm0, fmaxf(s[nt][0], s[nt][1]));
            tm1 = fmaxf(tm1, fmaxf(s[nt][2], s[nt][3]));
        }
        tm0 = fmaxf(tm0, __shfl_xor_sync(0xffffffffu, tm0, 1));
        tm0 = fmaxf(tm0, __shfl_xor_sync(0xffffffffu, tm0, 2));
        tm1 = fmaxf(tm1, __shfl_xor_sync(0xffffffffu, tm1, 1));
        tm1 = fmaxf(tm1, __shfl_xor_sync(0xffffffffu, tm1, 2));
        float mn0 = fmaxf(m0, tm0), mn1 = fmaxf(m1, tm1);
        float f0 = __expf(m0 - mn0), f1 = __expf(m1 - mn1);

        float ps0 = 0.f, ps1 = 0.f;
#pragma unroll
        for (int nt = 0; nt < 8; nt++) {
            s[nt][0] = __expf(s[nt][0] - mn0);
            s[nt][1] = __expf(s[nt][1] - mn0);
            s[nt][2] = __expf(s[nt][2] - mn1);
            s[nt][3] = __expf(s[nt][3] - mn1);
            ps0 += s[nt][0] + s[nt][1];
            ps1 += s[nt][2] + s[nt][3];
        }
        ps0 += __shfl_xor_sync(0xffffffffu, ps0, 1);
        ps0 += __shfl_xor_sync(0xffffffffu, ps0, 2);
        ps1 += __shfl_xor_sync(0xffffffffu, ps1, 1);
        ps1 += __shfl_xor_sync(0xffffffffu, ps1, 2);
        l0 = l0 * f0 + ps0;
        l1 = l1 * f1 + ps1;
        m0 = mn0; m1 = mn1;

        // rescale O accumulator
#pragma unroll
        for (int nt = 0; nt < 8; nt++) {
            acc_o[nt][0] *= f0; acc_o[nt][1] *= f0;
            acc_o[nt][2] *= f1; acc_o[nt][3] *= f1;
        }

        // ---- probs -> SMEM (k-major, warp-private columns) ----
#pragma unroll
        for (int nt = 0; nt < 8; nt++) {
            int jl = nt * 8 + 2 * kb;
            Sp[jl    ][wm + r]     = tf32r(s[nt][0]);
            Sp[jl + 1][wm + r]     = tf32r(s[nt][1]);
            Sp[jl    ][wm + r + 8] = tf32r(s[nt][2]);
            Sp[jl + 1][wm + r + 8] = tf32r(s[nt][3]);
        }
        __syncwarp();

        // ---- O += probs @ V ----
#pragma unroll
        for (int kj = 0; kj < 8; kj++) {
            float a[4];
            a[0] = Sp[kj * 8 + kb][wm + r];
            a[1] = Sp[kj * 8 + kb][wm + r + 8];
            a[2] = Sp[kj * 8 + kb + 4][wm + r];
            a[3] = Sp[kj * 8 + kb + 4][wm + r + 8];
            float bq[8][2];
#pragma unroll
            for (int nt = 0; nt < 8; nt++) {
                bq[nt][0] = Bv[kj * 8 + kb][nt * 8 + r];
                bq[nt][1] = Bv[kj * 8 + kb + 4][nt * 8 + r];
            }
#pragma unroll
            for (int nt = 0; nt < 8; nt++)
                mma8(acc_o[nt], a, bq[nt]);
        }
        __syncthreads();   // protect Bk/Bv/Sp before next tile
    }

    // ---- normalize and write ao ----
    float inv0 = 1.0f / l0, inv1 = 1.0f / l1;
#pragma unroll
    for (int nt = 0; nt < 8; nt++) {
        int c0 = nt * 8 + 2 * kb;
        float* o0 = ao + (size_t)(b * CSQ + row0) * HD + h * HDIM + c0;
        *(float2*)o0            = make_float2(acc_o[nt][0] * inv0, acc_o[nt][1] * inv0);
        *(float2*)(o0 + 8 * HD) = make_float2(acc_o[nt][2] * inv1, acc_o[nt][3] * inv1);
    }
}

// ---------------------------------------------------------------------------
// Launch: 6 kernels, default stream, graph-capturable.
// Inputs: input_, pos_embs, memory, u, v, W_kv, W_q, W_p, W_out, mask(unused).
// ---------------------------------------------------------------------------
extern "C" void kernel_launch(void* const* d_in, const int* in_sizes, int n_in,
                              void* d_out, int out_size)
{
    const float* input_ = (const float*)d_in[0];
    const float* pos    = (const float*)d_in[1];
    const float* memory = (const float*)d_in[2];
    const float* u      = (const float*)d_in[3];
    const float* v      = (const float*)d_in[4];
    const float* W_kv   = (const float*)d_in[5];
    const float* W_q    = (const float*)d_in[6];
    const float* W_p    = (const float*)d_in[7];
    const float* W_out  = (const float*)d_in[8];
    float* out = (float*)d_out;

    float *qb, *kvb, *pb, *Pb, *aob;
    cudaGetSymbolAddress((void**)&qb,  g_q);
    cudaGetSymbolAddress((void**)&kvb, g_kv);
    cudaGetSymbolAddress((void**)&pb,  g_p);
    cudaGetSymbolAddress((void**)&Pb,  g_P);
    cudaGetSymbolAddress((void**)&aob, g_ao);

    cudaFuncSetAttribute(attn_fused,
                         cudaFuncAttributeMaxDynamicSharedMemorySize, ATT_SMEM);

    dim3 thr(128);

    // q = input_ @ W_q                      (4096 x 1024 x 1024)
    gemm_tf32<0><<<dim3(HD / 128, LQG / 128), thr>>>(input_, nullptr, W_q, qb, LQG, HD, DIN);
    // kv = concat(memory, input_) @ W_kv    (8192 x 2048 x 1024)
    gemm_tf32<1><<<dim3(2 * HD / 128, (BSZ * TT) / 128), thr>>>(memory, input_, W_kv, kvb, BSZ * TT, 2 * HD, DIN);
    // p = pos_embs @ W_p                    (2048 x 1024 x 1024)
    gemm_tf32<0><<<dim3(HD / 128, TT / 128), thr>>>(pos, nullptr, W_p, pb, TT, HD, DIN);
    // P[h] = (q + v) @ p^T per head         (16 x 4096 x 2048 x 64)
    pos_gemm_tf32<<<dim3(TT / 128, LQG / 128, NH), thr>>>(qb, pb, v, Pb);
    // fused: scores + rel-shift + mask + online softmax + attn@V
    attn_fused<<<dim3(CSQ / 128, BSZ * NH), 256, ATT_SMEM>>>(qb, kvb, u, Pb, aob);
    // out = ao @ W_out                      (4096 x 1024 x 1024)
    gemm_tf32<0><<<dim3(DIN / 128, LQG / 128), thr>>>(aob, nullptr, W_out, out, LQG, DIN, HD);
}